// round 16
// baseline (speedup 1.0000x reference)
#include <cuda_runtime.h>
#include <cuda_fp16.h>
#include <cstdint>

#define N_NODES 100000
#define N_EDGES 3200000
#define F_IN    256
#define F_H     64
#define NB      391    // ceil(N_NODES/256)
#define PAD     128    // max neighbors stored per node (deg ~ Poisson(32))

// ---------------- scratch (device globals: allocation-free) ----------------
// g_fill is zero-initialized at load; aggregate re-zeroes it after use, so
// every kernel_launch (and every graph replay) starts with fill == 0.
__device__ __align__(16) __half g_Hs [(size_t)N_NODES * F_H];
__device__ __align__(16) float  g_ACC[(size_t)N_NODES * F_H];
__device__ int   g_fill[N_NODES];
__device__ __align__(16) int g_epad[(size_t)N_NODES * PAD];

// ---------------- padded-bucket scatter (self-detecting dtype) ----------------
__global__ void csr_kernel(const void* __restrict__ ei) {
    // dtype sniff: node ids < 2^17, so int64 data has all odd int32 words zero.
    const int* e32 = (const int*)ei;
    int ok64 = 1;
    #pragma unroll
    for (int i = 0; i < 8; ++i)
        if (e32[2 * i + 1] != 0) ok64 = 0;

    int e2 = blockIdx.x * blockDim.x + threadIdx.x;   // pair index
    if (e2 >= N_EDGES / 2) return;
    int s0, s1, d0, d1;
    if (ok64) {
        const longlong2* p = (const longlong2*)ei;
        longlong2 sp = p[e2];
        longlong2 dp = p[N_EDGES / 2 + e2];
        s0 = (int)sp.x; s1 = (int)sp.y;
        d0 = (int)dp.x; d1 = (int)dp.y;
    } else {
        const int2* p = (const int2*)ei;
        int2 sp = p[e2];
        int2 dp = p[N_EDGES / 2 + e2];
        s0 = sp.x; s1 = sp.y;
        d0 = dp.x; d1 = dp.y;
    }
    int p0 = atomicAdd(&g_fill[d0], 1);
    if (p0 < PAD) g_epad[(size_t)d0 * PAD + p0] = s0;
    int p1 = atomicAdd(&g_fill[d1], 1);
    if (p1 < PAD) g_epad[(size_t)d1 * PAD + p1] = s1;
}

// ---------------- HMMA GEMM: Hs = half(x @ W_gcn) (unscaled) ----------------
#define GM_M   128
#define XS_LD  72
#define WS_LD  72

__global__ __launch_bounds__(256) void gemm_kernel(
    const float* __restrict__ x, const float* __restrict__ W)
{
    __shared__ __half xs [2][GM_M * XS_LD];
    __shared__ __half wsT[2][64   * WS_LD];

    const int tid  = threadIdx.x;
    const int lane = tid & 31;
    const int warp = tid >> 5;
    const int base = blockIdx.x * GM_M;
    const int g = lane >> 2;
    const int t = lane & 3;
    const int wrow = warp * 16;
    const int r0 = tid >> 4;
    const int c  = tid & 15;

    float4 xr[8];
    float  wr[16];

    auto load_tile = [&](int kk) {
        #pragma unroll
        for (int rr = 0; rr < 8; ++rr) {
            int node = base + rr * 16 + r0;
            float4 v = make_float4(0.f, 0.f, 0.f, 0.f);
            if (node < N_NODES)
                v = *(const float4*)&x[(size_t)node * F_IN + kk + c * 4];
            xr[rr] = v;
        }
        #pragma unroll
        for (int p = 0; p < 16; ++p) {
            int i = tid + p * 256;
            int k = i >> 6, n = i & 63;
            wr[p] = W[(size_t)(kk + k) * 64 + n];
        }
    };
    auto store_tile = [&](int b) {
        #pragma unroll
        for (int rr = 0; rr < 8; ++rr) {
            __half2 h0 = __floats2half2_rn(xr[rr].x, xr[rr].y);
            __half2 h1 = __floats2half2_rn(xr[rr].z, xr[rr].w);
            uint2 u;
            u.x = *(uint32_t*)&h0;
            u.y = *(uint32_t*)&h1;
            *(uint2*)&xs[b][(rr * 16 + r0) * XS_LD + c * 4] = u;
        }
        #pragma unroll
        for (int p = 0; p < 16; ++p) {
            int i = tid + p * 256;
            int k = i >> 6, n = i & 63;
            wsT[b][n * WS_LD + k] = __float2half(wr[p]);
        }
    };

    float acc[8][4];
    #pragma unroll
    for (int i = 0; i < 8; ++i)
        #pragma unroll
        for (int j = 0; j < 4; ++j) acc[i][j] = 0.0f;

    load_tile(0);
    store_tile(0);

    #pragma unroll
    for (int kt = 0; kt < 4; ++kt) {
        __syncthreads();
        if (kt < 3) load_tile((kt + 1) * 64);
        const int b = kt & 1;

        #pragma unroll
        for (int ks = 0; ks < 4; ++ks) {
            const int K0 = ks * 16;
            uint32_t a0 = *(const uint32_t*)&xs[b][(wrow + g    ) * XS_LD + K0 +     2 * t];
            uint32_t a1 = *(const uint32_t*)&xs[b][(wrow + g + 8) * XS_LD + K0 +     2 * t];
            uint32_t a2 = *(const uint32_t*)&xs[b][(wrow + g    ) * XS_LD + K0 + 8 + 2 * t];
            uint32_t a3 = *(const uint32_t*)&xs[b][(wrow + g + 8) * XS_LD + K0 + 8 + 2 * t];
            #pragma unroll
            for (int nt = 0; nt < 8; ++nt) {
                uint32_t b0 = *(const uint32_t*)&wsT[b][(nt * 8 + g) * WS_LD + K0 +     2 * t];
                uint32_t b1 = *(const uint32_t*)&wsT[b][(nt * 8 + g) * WS_LD + K0 + 8 + 2 * t];
                asm volatile(
                    "mma.sync.aligned.m16n8k16.row.col.f32.f16.f16.f32 "
                    "{%0,%1,%2,%3}, {%4,%5,%6,%7}, {%8,%9}, {%0,%1,%2,%3};"
                    : "+f"(acc[nt][0]), "+f"(acc[nt][1]),
                      "+f"(acc[nt][2]), "+f"(acc[nt][3])
                    : "r"(a0), "r"(a1), "r"(a2), "r"(a3), "r"(b0), "r"(b1));
            }
        }
        if (kt < 3) store_tile(1 - b);
    }

    int n0 = base + wrow + g;
    int n1 = n0 + 8;
    #pragma unroll
    for (int nt = 0; nt < 8; ++nt) {
        if (n0 < N_NODES) {
            __half2 h = __floats2half2_rn(acc[nt][0], acc[nt][1]);
            *(uint32_t*)&g_Hs[(size_t)n0 * F_H + nt * 8 + 2 * t] = *(uint32_t*)&h;
        }
        if (n1 < N_NODES) {
            __half2 h = __floats2half2_rn(acc[nt][2], acc[nt][3]);
            *(uint32_t*)&g_Hs[(size_t)n1 * F_H + nt * 8 + 2 * t] = *(uint32_t*)&h;
        }
    }
}

// ---------------- scale H by dinv in fp32 (H' = dinv[n] * H[n]) ----------------
__global__ __launch_bounds__(256) void scale_kernel() {
    int idx = blockIdx.x * 256 + threadIdx.x;       // over N_NODES*8 uint4
    if (idx >= N_NODES * 8) return;
    int n = idx >> 3;
    float s = rsqrtf((float)g_fill[n] + 1.0f);
    uint4* H = (uint4*)g_Hs;
    uint4 r = H[idx];
    __half2* p = (__half2*)&r;
    #pragma unroll
    for (int j = 0; j < 4; ++j) {
        float2 f = __half22float2(p[j]);
        p[j] = __floats2half2_rn(f.x * s, f.y * s);
    }
    H[idx] = r;
}

// ---------------- aggregate v10: v8 layout + pipelined index prefetch ----
__device__ __forceinline__ void add_row8(float* a, uint4 r) {
    float2 f;
    f = __half22float2(*(__half2*)&r.x); a[0] += f.x; a[1] += f.y;
    f = __half22float2(*(__half2*)&r.y); a[2] += f.x; a[3] += f.y;
    f = __half22float2(*(__half2*)&r.z); a[4] += f.x; a[5] += f.y;
    f = __half22float2(*(__half2*)&r.w); a[6] += f.x; a[7] += f.y;
}

__device__ __forceinline__ uint4 hadd4(uint4 a, uint4 b) {
    uint4 o;
    const __half2* pa = (const __half2*)&a;
    const __half2* pb = (const __half2*)&b;
    __half2* po = (__half2*)&o;
    #pragma unroll
    for (int j = 0; j < 4; ++j) po[j] = __hadd2(pa[j], pb[j]);
    return o;
}

__device__ __forceinline__ uint4 ldH(const char* Hb, int s, int q) {
    // 32-bit byte offset: s*128 + q*16 < 2^32
    unsigned off = (unsigned)s * 128u + (unsigned)q * 16u;
    return *(const uint4*)(Hb + off);
}

__global__ __launch_bounds__(256) void aggregate_kernel() {
    int w = blockIdx.x * 8 + (threadIdx.x >> 5);
    if (w >= N_NODES) return;
    const int lane = threadIdx.x & 31;
    const int st = lane >> 3;
    const int q  = lane & 7;

    const char* __restrict__ Hb = (const char*)g_Hs;
    const int fill = g_fill[w];
    const float dv = rsqrtf((float)fill + 1.0f);

    float acc[8] = {0.f, 0.f, 0.f, 0.f, 0.f, 0.f, 0.f, 0.f};
    if (st == 0) {
        add_row8(acc, ldH(Hb, w, q));           // self-loop term (H'[w])
    }

    int cnt = fill;
    if (cnt > PAD) cnt = PAD;
    const int beg = w * PAD;
    const int end = beg + cnt;
    int i = beg + st;

    // quad loop with index prefetch: same interleaved (coalesced) layout as v8
    int s0, s1, s2, s3;
    bool have = (i + 12 < end);
    if (have) {
        s0 = g_epad[i];
        s1 = g_epad[i + 4];
        s2 = g_epad[i + 8];
        s3 = g_epad[i + 12];
    }
    while (have) {
        const int ni = i + 16;
        const bool nhave = (ni + 12 < end);
        // issue row loads for current indices
        uint4 r0 = ldH(Hb, s0, q);
        uint4 r1 = ldH(Hb, s1, q);
        uint4 r2 = ldH(Hb, s2, q);
        uint4 r3 = ldH(Hb, s3, q);
        // prefetch next iteration's indices while rows are in flight
        if (nhave) {
            s0 = g_epad[ni];
            s1 = g_epad[ni + 4];
            s2 = g_epad[ni + 8];
            s3 = g_epad[ni + 12];
        }
        // independent pair trees
        uint4 h01 = hadd4(r0, r1);
        uint4 h23 = hadd4(r2, r3);
        add_row8(acc, h01);
        add_row8(acc, h23);
        i = ni;
        have = nhave;
    }
    // pair remainder: depth-1 tree
    for (; i + 4 < end; i += 8) {
        int t0 = g_epad[i];
        int t1 = g_epad[i + 4];
        uint4 r0 = ldH(Hb, t0, q);
        uint4 r1 = ldH(Hb, t1, q);
        add_row8(acc, hadd4(r0, r1));
    }
    // single remainder
    if (i < end) {
        add_row8(acc, ldH(Hb, g_epad[i], q));
    }

    #pragma unroll
    for (int k = 0; k < 8; ++k) {
        acc[k] += __shfl_xor_sync(0xffffffffu, acc[k], 8);
        acc[k] += __shfl_xor_sync(0xffffffffu, acc[k], 16);
    }

    // reset fill for the next graph replay (all lanes' reads are done)
    __syncwarp();
    if (lane == 0) g_fill[w] = 0;

    if (st == 0) {
        float4 o0 = make_float4(acc[0] * dv, acc[1] * dv, acc[2] * dv, acc[3] * dv);
        float4 o1 = make_float4(acc[4] * dv, acc[5] * dv, acc[6] * dv, acc[7] * dv);
        ((float4*)g_ACC)[(size_t)w * 16 + q * 2]     = o0;
        ((float4*)g_ACC)[(size_t)w * 16 + q * 2 + 1] = o1;
    }
}

// ---------------- fused ReLU + MLP 64->32->16->10 (vectorized weights) ----------------
__global__ __launch_bounds__(256) void mlp_kernel(
    const float* __restrict__ b_gcn,
    const float* __restrict__ W1, const float* __restrict__ b1,
    const float* __restrict__ W2, const float* __restrict__ b2,
    const float* __restrict__ W3, const float* __restrict__ b3,
    float* __restrict__ out)
{
    __shared__ __align__(16) float sW1[64 * 32];
    __shared__ __align__(16) float sW2[32 * 16];
    __shared__ __align__(16) float sW3[16 * 10];
    __shared__ float sbg[64], sb1[32], sb2[16], sb3[10];

    const int tid = threadIdx.x;
    for (int i = tid; i < 64 * 32; i += 256) sW1[i] = W1[i];
    for (int i = tid; i < 32 * 16; i += 256) sW2[i] = W2[i];
    for (int i = tid; i < 16 * 10; i += 256) sW3[i] = W3[i];
    if (tid < 64) sbg[tid] = b_gcn[tid];
    if (tid < 32) sb1[tid] = b1[tid];
    if (tid < 16) sb2[tid] = b2[tid];
    if (tid < 10) sb3[tid] = b3[tid];
    __syncthreads();

    int node = blockIdx.x * 256 + tid;
    if (node >= N_NODES) return;

    float in[64];
    const float4* A4 = (const float4*)g_ACC;
    #pragma unroll
    for (int q = 0; q < 16; ++q) {
        float4 v = A4[(size_t)node * 16 + q];
        in[4 * q + 0] = fmaxf(v.x + sbg[4 * q + 0], 0.0f);
        in[4 * q + 1] = fmaxf(v.y + sbg[4 * q + 1], 0.0f);
        in[4 * q + 2] = fmaxf(v.z + sbg[4 * q + 2], 0.0f);
        in[4 * q + 3] = fmaxf(v.w + sbg[4 * q + 3], 0.0f);
    }

    float h1[32];
    #pragma unroll
    for (int j = 0; j < 32; ++j) h1[j] = sb1[j];
    #pragma unroll
    for (int k = 0; k < 64; ++k) {
        float a = in[k];
        #pragma unroll
        for (int j4 = 0; j4 < 8; ++j4) {
            float4 wv = *(const float4*)&sW1[k * 32 + j4 * 4];
            h1[j4 * 4 + 0] = fmaf(a, wv.x, h1[j4 * 4 + 0]);
            h1[j4 * 4 + 1] = fmaf(a, wv.y, h1[j4 * 4 + 1]);
            h1[j4 * 4 + 2] = fmaf(a, wv.z, h1[j4 * 4 + 2]);
            h1[j4 * 4 + 3] = fmaf(a, wv.w, h1[j4 * 4 + 3]);
        }
    }
    #pragma unroll
    for (int j = 0; j < 32; ++j) h1[j] = fmaxf(h1[j], 0.0f);

    float h2[16];
    #pragma unroll
    for (int j = 0; j < 16; ++j) h2[j] = sb2[j];
    #pragma unroll
    for (int k = 0; k < 32; ++k) {
        float a = h1[k];
        #pragma unroll
        for (int j4 = 0; j4 < 4; ++j4) {
            float4 wv = *(const float4*)&sW2[k * 16 + j4 * 4];
            h2[j4 * 4 + 0] = fmaf(a, wv.x, h2[j4 * 4 + 0]);
            h2[j4 * 4 + 1] = fmaf(a, wv.y, h2[j4 * 4 + 1]);
            h2[j4 * 4 + 2] = fmaf(a, wv.z, h2[j4 * 4 + 2]);
            h2[j4 * 4 + 3] = fmaf(a, wv.w, h2[j4 * 4 + 3]);
        }
    }
    #pragma unroll
    for (int j = 0; j < 16; ++j) h2[j] = fmaxf(h2[j], 0.0f);

    float o[10];
    #pragma unroll
    for (int j = 0; j < 10; ++j) o[j] = sb3[j];
    #pragma unroll
    for (int k = 0; k < 16; ++k) {
        float a = h2[k];
        #pragma unroll
        for (int j2 = 0; j2 < 5; ++j2) {
            float2 wv = *(const float2*)&sW3[k * 10 + j2 * 2];
            o[j2 * 2 + 0] = fmaf(a, wv.x, o[j2 * 2 + 0]);
            o[j2 * 2 + 1] = fmaf(a, wv.y, o[j2 * 2 + 1]);
        }
    }
    #pragma unroll
    for (int j = 0; j < 10; ++j) out[(size_t)node * 10 + j] = o[j];
}

// ---------------- launcher: 5 launches, 2 events ----------------
extern "C" void kernel_launch(void* const* d_in, const int* in_sizes, int n_in,
                              void* d_out, int out_size)
{
    const float* x     = (const float*)d_in[0];
    const void*  ei    = d_in[1];
    const float* W_gcn = (const float*)d_in[2];
    const float* b_gcn = (const float*)d_in[3];
    const float* W1    = (const float*)d_in[4];
    const float* b1    = (const float*)d_in[5];
    const float* W2    = (const float*)d_in[6];
    const float* b2    = (const float*)d_in[7];
    const float* W3    = (const float*)d_in[8];
    const float* b3    = (const float*)d_in[9];
    float* out = (float*)d_out;

    static cudaStream_t s2 = []() {
        cudaStream_t s; cudaStreamCreateWithFlags(&s, cudaStreamNonBlocking); return s;
    }();
    static cudaEvent_t evFork = []() {
        cudaEvent_t e; cudaEventCreateWithFlags(&e, cudaEventDisableTiming); return e;
    }();
    static cudaEvent_t evGemm = []() {
        cudaEvent_t e; cudaEventCreateWithFlags(&e, cudaEventDisableTiming); return e;
    }();

    // fork GEMM immediately (no dependencies)
    cudaEventRecord(evFork, 0);
    cudaStreamWaitEvent(s2, evFork, 0);
    gemm_kernel<<<(N_NODES + GM_M - 1) / GM_M, 256, 0, s2>>>(x, W_gcn);
    cudaEventRecord(evGemm, s2);

    // main: padded scatter (g_fill starts zeroed; aggregate re-zeroes it)
    csr_kernel<<<(N_EDGES / 2 + 255) / 256, 256>>>(ei);

    // main: join GEMM, then scale -> aggregate -> mlp
    cudaStreamWaitEvent(0, evGemm, 0);
    scale_kernel<<<(N_NODES * 8 + 255) / 256, 256>>>();
    aggregate_kernel<<<(N_NODES + 7) / 8, 256>>>();
    mlp_kernel<<<(N_NODES + 255) / 256, 256>>>(b_gcn, W1, b1, W2, b2, W3, b3, out);
}

// round 17
// speedup vs baseline: 1.0834x; 1.0834x over previous
#include <cuda_runtime.h>
#include <cuda_fp16.h>
#include <cstdint>

#define N_NODES 100000
#define N_EDGES 3200000
#define F_IN    256
#define F_H     64
#define NB      391    // ceil(N_NODES/256)
#define PAD     128    // max neighbors stored per node (deg ~ Poisson(32))

// ---------------- scratch (device globals: allocation-free) ----------------
// g_fill is zero-initialized at load; aggregate re-zeroes it after use, so
// every kernel_launch (and every graph replay) starts with fill == 0.
__device__ __align__(16) __half g_Hs [(size_t)N_NODES * F_H];
__device__ __align__(16) float  g_ACC[(size_t)N_NODES * F_H];
__device__ int   g_fill[N_NODES];
__device__ __align__(16) int g_epad[(size_t)N_NODES * PAD];

// ---------------- padded-bucket scatter (self-detecting dtype) ----------------
__global__ void csr_kernel(const void* __restrict__ ei) {
    // dtype sniff: node ids < 2^17, so int64 data has all odd int32 words zero.
    const int* e32 = (const int*)ei;
    int ok64 = 1;
    #pragma unroll
    for (int i = 0; i < 8; ++i)
        if (e32[2 * i + 1] != 0) ok64 = 0;

    int e2 = blockIdx.x * blockDim.x + threadIdx.x;   // pair index
    if (e2 >= N_EDGES / 2) return;
    int s0, s1, d0, d1;
    if (ok64) {
        const longlong2* p = (const longlong2*)ei;
        longlong2 sp = p[e2];
        longlong2 dp = p[N_EDGES / 2 + e2];
        s0 = (int)sp.x; s1 = (int)sp.y;
        d0 = (int)dp.x; d1 = (int)dp.y;
    } else {
        const int2* p = (const int2*)ei;
        int2 sp = p[e2];
        int2 dp = p[N_EDGES / 2 + e2];
        s0 = sp.x; s1 = sp.y;
        d0 = dp.x; d1 = dp.y;
    }
    int p0 = atomicAdd(&g_fill[d0], 1);
    if (p0 < PAD) g_epad[(size_t)d0 * PAD + p0] = s0;
    int p1 = atomicAdd(&g_fill[d1], 1);
    if (p1 < PAD) g_epad[(size_t)d1 * PAD + p1] = s1;
}

// ---------------- HMMA GEMM: Hs = half(x @ W_gcn) (unscaled) ----------------
#define GM_M   128
#define XS_LD  72
#define WS_LD  72

__global__ __launch_bounds__(256) void gemm_kernel(
    const float* __restrict__ x, const float* __restrict__ W)
{
    __shared__ __half xs [2][GM_M * XS_LD];
    __shared__ __half wsT[2][64   * WS_LD];

    const int tid  = threadIdx.x;
    const int lane = tid & 31;
    const int warp = tid >> 5;
    const int base = blockIdx.x * GM_M;
    const int g = lane >> 2;
    const int t = lane & 3;
    const int wrow = warp * 16;
    const int r0 = tid >> 4;
    const int c  = tid & 15;

    float4 xr[8];
    float  wr[16];

    auto load_tile = [&](int kk) {
        #pragma unroll
        for (int rr = 0; rr < 8; ++rr) {
            int node = base + rr * 16 + r0;
            float4 v = make_float4(0.f, 0.f, 0.f, 0.f);
            if (node < N_NODES)
                v = *(const float4*)&x[(size_t)node * F_IN + kk + c * 4];
            xr[rr] = v;
        }
        #pragma unroll
        for (int p = 0; p < 16; ++p) {
            int i = tid + p * 256;
            int k = i >> 6, n = i & 63;
            wr[p] = W[(size_t)(kk + k) * 64 + n];
        }
    };
    auto store_tile = [&](int b) {
        #pragma unroll
        for (int rr = 0; rr < 8; ++rr) {
            __half2 h0 = __floats2half2_rn(xr[rr].x, xr[rr].y);
            __half2 h1 = __floats2half2_rn(xr[rr].z, xr[rr].w);
            uint2 u;
            u.x = *(uint32_t*)&h0;
            u.y = *(uint32_t*)&h1;
            *(uint2*)&xs[b][(rr * 16 + r0) * XS_LD + c * 4] = u;
        }
        #pragma unroll
        for (int p = 0; p < 16; ++p) {
            int i = tid + p * 256;
            int k = i >> 6, n = i & 63;
            wsT[b][n * WS_LD + k] = __float2half(wr[p]);
        }
    };

    float acc[8][4];
    #pragma unroll
    for (int i = 0; i < 8; ++i)
        #pragma unroll
        for (int j = 0; j < 4; ++j) acc[i][j] = 0.0f;

    load_tile(0);
    store_tile(0);

    #pragma unroll
    for (int kt = 0; kt < 4; ++kt) {
        __syncthreads();
        if (kt < 3) load_tile((kt + 1) * 64);
        const int b = kt & 1;

        #pragma unroll
        for (int ks = 0; ks < 4; ++ks) {
            const int K0 = ks * 16;
            uint32_t a0 = *(const uint32_t*)&xs[b][(wrow + g    ) * XS_LD + K0 +     2 * t];
            uint32_t a1 = *(const uint32_t*)&xs[b][(wrow + g + 8) * XS_LD + K0 +     2 * t];
            uint32_t a2 = *(const uint32_t*)&xs[b][(wrow + g    ) * XS_LD + K0 + 8 + 2 * t];
            uint32_t a3 = *(const uint32_t*)&xs[b][(wrow + g + 8) * XS_LD + K0 + 8 + 2 * t];
            #pragma unroll
            for (int nt = 0; nt < 8; ++nt) {
                uint32_t b0 = *(const uint32_t*)&wsT[b][(nt * 8 + g) * WS_LD + K0 +     2 * t];
                uint32_t b1 = *(const uint32_t*)&wsT[b][(nt * 8 + g) * WS_LD + K0 + 8 + 2 * t];
                asm volatile(
                    "mma.sync.aligned.m16n8k16.row.col.f32.f16.f16.f32 "
                    "{%0,%1,%2,%3}, {%4,%5,%6,%7}, {%8,%9}, {%0,%1,%2,%3};"
                    : "+f"(acc[nt][0]), "+f"(acc[nt][1]),
                      "+f"(acc[nt][2]), "+f"(acc[nt][3])
                    : "r"(a0), "r"(a1), "r"(a2), "r"(a3), "r"(b0), "r"(b1));
            }
        }
        if (kt < 3) store_tile(1 - b);
    }

    int n0 = base + wrow + g;
    int n1 = n0 + 8;
    #pragma unroll
    for (int nt = 0; nt < 8; ++nt) {
        if (n0 < N_NODES) {
            __half2 h = __floats2half2_rn(acc[nt][0], acc[nt][1]);
            *(uint32_t*)&g_Hs[(size_t)n0 * F_H + nt * 8 + 2 * t] = *(uint32_t*)&h;
        }
        if (n1 < N_NODES) {
            __half2 h = __floats2half2_rn(acc[nt][2], acc[nt][3]);
            *(uint32_t*)&g_Hs[(size_t)n1 * F_H + nt * 8 + 2 * t] = *(uint32_t*)&h;
        }
    }
}

// ---------------- scale H by dinv in fp32 (H' = dinv[n] * H[n]) ----------------
__global__ __launch_bounds__(256) void scale_kernel() {
    int idx = blockIdx.x * 256 + threadIdx.x;       // over N_NODES*8 uint4
    if (idx >= N_NODES * 8) return;
    int n = idx >> 3;
    float s = rsqrtf((float)g_fill[n] + 1.0f);
    uint4* H = (uint4*)g_Hs;
    uint4 r = H[idx];
    __half2* p = (__half2*)&r;
    #pragma unroll
    for (int j = 0; j < 4; ++j) {
        float2 f = __half22float2(p[j]);
        p[j] = __floats2half2_rn(f.x * s, f.y * s);
    }
    H[idx] = r;
}

// ---------------- aggregate v8 (measured optimum) + streaming index loads ----
__device__ __forceinline__ void add_row8(float* a, uint4 r) {
    float2 f;
    f = __half22float2(*(__half2*)&r.x); a[0] += f.x; a[1] += f.y;
    f = __half22float2(*(__half2*)&r.y); a[2] += f.x; a[3] += f.y;
    f = __half22float2(*(__half2*)&r.z); a[4] += f.x; a[5] += f.y;
    f = __half22float2(*(__half2*)&r.w); a[6] += f.x; a[7] += f.y;
}

__device__ __forceinline__ uint4 hadd4(uint4 a, uint4 b) {
    uint4 o;
    const __half2* pa = (const __half2*)&a;
    const __half2* pb = (const __half2*)&b;
    __half2* po = (__half2*)&o;
    #pragma unroll
    for (int j = 0; j < 4; ++j) po[j] = __hadd2(pa[j], pb[j]);
    return o;
}

__device__ __forceinline__ uint4 ldH(const char* Hb, int s, int q) {
    // 32-bit byte offset: s*128 + q*16 < 2^32
    unsigned off = (unsigned)s * 128u + (unsigned)q * 16u;
    return *(const uint4*)(Hb + off);
}

__global__ __launch_bounds__(256) void aggregate_kernel() {
    int w = blockIdx.x * 8 + (threadIdx.x >> 5);
    if (w >= N_NODES) return;
    const int lane = threadIdx.x & 31;
    const int st = lane >> 3;
    const int q  = lane & 7;

    const char* __restrict__ Hb = (const char*)g_Hs;
    const int fill = g_fill[w];
    const float dv = rsqrtf((float)fill + 1.0f);

    float acc[8] = {0.f, 0.f, 0.f, 0.f, 0.f, 0.f, 0.f, 0.f};
    if (st == 0) {
        add_row8(acc, ldH(Hb, w, q));           // self-loop term (H'[w])
    }

    int cnt = fill;
    if (cnt > PAD) cnt = PAD;
    const int beg = w * PAD;
    const int end = beg + cnt;
    int i = beg + st;
    // quad loop: two INDEPENDENT depth-1 pair trees per iteration
    for (; i + 12 < end; i += 16) {
        int s0 = __ldcs(&g_epad[i]);
        int s1 = __ldcs(&g_epad[i + 4]);
        int s2 = __ldcs(&g_epad[i + 8]);
        int s3 = __ldcs(&g_epad[i + 12]);
        uint4 r0 = ldH(Hb, s0, q);
        uint4 r1 = ldH(Hb, s1, q);
        uint4 r2 = ldH(Hb, s2, q);
        uint4 r3 = ldH(Hb, s3, q);
        uint4 h01 = hadd4(r0, r1);
        uint4 h23 = hadd4(r2, r3);
        add_row8(acc, h01);
        add_row8(acc, h23);
    }
    // pair remainder: depth-1 tree
    for (; i + 4 < end; i += 8) {
        int s0 = __ldcs(&g_epad[i]);
        int s1 = __ldcs(&g_epad[i + 4]);
        uint4 r0 = ldH(Hb, s0, q);
        uint4 r1 = ldH(Hb, s1, q);
        add_row8(acc, hadd4(r0, r1));
    }
    // single remainder
    if (i < end) {
        add_row8(acc, ldH(Hb, __ldcs(&g_epad[i]), q));
    }

    #pragma unroll
    for (int j = 0; j < 8; ++j) {
        acc[j] += __shfl_xor_sync(0xffffffffu, acc[j], 8);
        acc[j] += __shfl_xor_sync(0xffffffffu, acc[j], 16);
    }

    // reset fill for the next graph replay (all lanes' reads are done)
    __syncwarp();
    if (lane == 0) g_fill[w] = 0;

    if (st == 0) {
        float4 o0 = make_float4(acc[0] * dv, acc[1] * dv, acc[2] * dv, acc[3] * dv);
        float4 o1 = make_float4(acc[4] * dv, acc[5] * dv, acc[6] * dv, acc[7] * dv);
        ((float4*)g_ACC)[(size_t)w * 16 + q * 2]     = o0;
        ((float4*)g_ACC)[(size_t)w * 16 + q * 2 + 1] = o1;
    }
}

// ---------------- fused ReLU + MLP 64->32->16->10 (vectorized weights) ----------------
__global__ __launch_bounds__(256) void mlp_kernel(
    const float* __restrict__ b_gcn,
    const float* __restrict__ W1, const float* __restrict__ b1,
    const float* __restrict__ W2, const float* __restrict__ b2,
    const float* __restrict__ W3, const float* __restrict__ b3,
    float* __restrict__ out)
{
    __shared__ __align__(16) float sW1[64 * 32];
    __shared__ __align__(16) float sW2[32 * 16];
    __shared__ __align__(16) float sW3[16 * 10];
    __shared__ float sbg[64], sb1[32], sb2[16], sb3[10];

    const int tid = threadIdx.x;
    for (int i = tid; i < 64 * 32; i += 256) sW1[i] = W1[i];
    for (int i = tid; i < 32 * 16; i += 256) sW2[i] = W2[i];
    for (int i = tid; i < 16 * 10; i += 256) sW3[i] = W3[i];
    if (tid < 64) sbg[tid] = b_gcn[tid];
    if (tid < 32) sb1[tid] = b1[tid];
    if (tid < 16) sb2[tid] = b2[tid];
    if (tid < 10) sb3[tid] = b3[tid];
    __syncthreads();

    int node = blockIdx.x * 256 + tid;
    if (node >= N_NODES) return;

    float in[64];
    const float4* A4 = (const float4*)g_ACC;
    #pragma unroll
    for (int q = 0; q < 16; ++q) {
        float4 v = A4[(size_t)node * 16 + q];
        in[4 * q + 0] = fmaxf(v.x + sbg[4 * q + 0], 0.0f);
        in[4 * q + 1] = fmaxf(v.y + sbg[4 * q + 1], 0.0f);
        in[4 * q + 2] = fmaxf(v.z + sbg[4 * q + 2], 0.0f);
        in[4 * q + 3] = fmaxf(v.w + sbg[4 * q + 3], 0.0f);
    }

    float h1[32];
    #pragma unroll
    for (int j = 0; j < 32; ++j) h1[j] = sb1[j];
    #pragma unroll
    for (int k = 0; k < 64; ++k) {
        float a = in[k];
        #pragma unroll
        for (int j4 = 0; j4 < 8; ++j4) {
            float4 wv = *(const float4*)&sW1[k * 32 + j4 * 4];
            h1[j4 * 4 + 0] = fmaf(a, wv.x, h1[j4 * 4 + 0]);
            h1[j4 * 4 + 1] = fmaf(a, wv.y, h1[j4 * 4 + 1]);
            h1[j4 * 4 + 2] = fmaf(a, wv.z, h1[j4 * 4 + 2]);
            h1[j4 * 4 + 3] = fmaf(a, wv.w, h1[j4 * 4 + 3]);
        }
    }
    #pragma unroll
    for (int j = 0; j < 32; ++j) h1[j] = fmaxf(h1[j], 0.0f);

    float h2[16];
    #pragma unroll
    for (int j = 0; j < 16; ++j) h2[j] = sb2[j];
    #pragma unroll
    for (int k = 0; k < 32; ++k) {
        float a = h1[k];
        #pragma unroll
        for (int j4 = 0; j4 < 4; ++j4) {
            float4 wv = *(const float4*)&sW2[k * 16 + j4 * 4];
            h2[j4 * 4 + 0] = fmaf(a, wv.x, h2[j4 * 4 + 0]);
            h2[j4 * 4 + 1] = fmaf(a, wv.y, h2[j4 * 4 + 1]);
            h2[j4 * 4 + 2] = fmaf(a, wv.z, h2[j4 * 4 + 2]);
            h2[j4 * 4 + 3] = fmaf(a, wv.w, h2[j4 * 4 + 3]);
        }
    }
    #pragma unroll
    for (int j = 0; j < 16; ++j) h2[j] = fmaxf(h2[j], 0.0f);

    float o[10];
    #pragma unroll
    for (int j = 0; j < 10; ++j) o[j] = sb3[j];
    #pragma unroll
    for (int k = 0; k < 16; ++k) {
        float a = h2[k];
        #pragma unroll
        for (int j2 = 0; j2 < 5; ++j2) {
            float2 wv = *(const float2*)&sW3[k * 10 + j2 * 2];
            o[j2 * 2 + 0] = fmaf(a, wv.x, o[j2 * 2 + 0]);
            o[j2 * 2 + 1] = fmaf(a, wv.y, o[j2 * 2 + 1]);
        }
    }
    #pragma unroll
    for (int j = 0; j < 10; ++j) out[(size_t)node * 10 + j] = o[j];
}

// ---------------- launcher: 5 launches, 2 events ----------------
extern "C" void kernel_launch(void* const* d_in, const int* in_sizes, int n_in,
                              void* d_out, int out_size)
{
    const float* x     = (const float*)d_in[0];
    const void*  ei    = d_in[1];
    const float* W_gcn = (const float*)d_in[2];
    const float* b_gcn = (const float*)d_in[3];
    const float* W1    = (const float*)d_in[4];
    const float* b1    = (const float*)d_in[5];
    const float* W2    = (const float*)d_in[6];
    const float* b2    = (const float*)d_in[7];
    const float* W3    = (const float*)d_in[8];
    const float* b3    = (const float*)d_in[9];
    float* out = (float*)d_out;

    static cudaStream_t s2 = []() {
        cudaStream_t s; cudaStreamCreateWithFlags(&s, cudaStreamNonBlocking); return s;
    }();
    static cudaEvent_t evFork = []() {
        cudaEvent_t e; cudaEventCreateWithFlags(&e, cudaEventDisableTiming); return e;
    }();
    static cudaEvent_t evGemm = []() {
        cudaEvent_t e; cudaEventCreateWithFlags(&e, cudaEventDisableTiming); return e;
    }();

    // fork GEMM immediately (no dependencies)
    cudaEventRecord(evFork, 0);
    cudaStreamWaitEvent(s2, evFork, 0);
    gemm_kernel<<<(N_NODES + GM_M - 1) / GM_M, 256, 0, s2>>>(x, W_gcn);
    cudaEventRecord(evGemm, s2);

    // main: padded scatter (g_fill starts zeroed; aggregate re-zeroes it)
    csr_kernel<<<(N_EDGES / 2 + 255) / 256, 256>>>(ei);

    // main: join GEMM, then scale -> aggregate -> mlp
    cudaStreamWaitEvent(0, evGemm, 0);
    scale_kernel<<<(N_NODES * 8 + 255) / 256, 256>>>();
    aggregate_kernel<<<(N_NODES + 7) / 8, 256>>>();
    mlp_kernel<<<(N_NODES + 255) / 256, 256>>>(b_gcn, W1, b1, W2, b2, W3, b3, out);
}